// round 1
// baseline (speedup 1.0000x reference)
#include <cuda_runtime.h>
#include <math.h>

#define B_   8
#define N_   1024
#define C_   768
#define H_   12
#define D_   64
#define HID_ 3072
#define BNC  6291456      /* B*N*C        */
#define BN3C 18874368     /* B*N*3C       */
#define SSZ  100663296    /* B*H*N*N      */
#define HSZ  25165824     /* B*N*HIDDEN   */

// ---------------- scratch (device globals; no allocation) ----------------
__device__ float g_xn0[BNC], g_xn1[BNC];
__device__ float g_qkv0[BN3C], g_qkv1[BN3C];
__device__ float g_q0[BNC], g_k0[BNC], g_v0[BNC];
__device__ float g_q1[BNC], g_k1[BNC], g_v1[BNC];
__device__ float g_S[SSZ];
__device__ float g_ctx[BNC], g_ctxT[BNC];
__device__ float g_o0[BNC], g_o1[BNC];
__device__ float g_y[BNC];
__device__ float g_h[HSZ];

// ---------------- LayerNorm over 768 (one block per row) ----------------
__global__ void __launch_bounds__(256) ln768_kernel(
    const float* __restrict__ x, const float* __restrict__ w,
    const float* __restrict__ b, float* __restrict__ y)
{
    const int row = blockIdx.x;
    const float* xr = x + (long)row * C_;
    float* yr = y + (long)row * C_;
    const int t = threadIdx.x;

    float v[3];
    float s = 0.f, s2 = 0.f;
#pragma unroll
    for (int i = 0; i < 3; i++) {
        float tv = xr[t + i * 256];
        v[i] = tv; s += tv; s2 += tv * tv;
    }
#pragma unroll
    for (int o = 16; o > 0; o >>= 1) {
        s  += __shfl_xor_sync(~0u, s, o);
        s2 += __shfl_xor_sync(~0u, s2, o);
    }
    __shared__ float red[16];
    __shared__ float mu_s, rs_s;
    int wid = t >> 5, lid = t & 31;
    if (lid == 0) { red[wid] = s; red[8 + wid] = s2; }
    __syncthreads();
    if (t == 0) {
        float S = 0.f, S2 = 0.f;
#pragma unroll
        for (int i = 0; i < 8; i++) { S += red[i]; S2 += red[8 + i]; }
        float mu = S / C_;
        float var = S2 / C_ - mu * mu;
        mu_s = mu; rs_s = rsqrtf(var + 1e-5f);
    }
    __syncthreads();
    float mu = mu_s, rs = rs_s;
#pragma unroll
    for (int i = 0; i < 3; i++) {
        int c = t + i * 256;
        yr[c] = (v[i] - mu) * rs * w[c] + b[c];
    }
}

// ---------------- per-head LN (64 elems, one warp per row) ----------------
// input: qkv (B,N,3,H,64) contiguous; output q/k/v in (B,H,N,64)
__global__ void __launch_bounds__(256) headln_kernel(
    const float* __restrict__ qkv0, const float* __restrict__ qkv1,
    const float* __restrict__ w, const float* __restrict__ b,
    float* __restrict__ q0, float* __restrict__ k0, float* __restrict__ v0,
    float* __restrict__ q1, float* __restrict__ k1, float* __restrict__ v1)
{
    const int ROWS = 2 * B_ * N_ * 3 * H_;
    int warp = (blockIdx.x * 256 + threadIdx.x) >> 5;
    int lane = threadIdx.x & 31;
    if (warp >= ROWS) return;

    int st = warp / (B_ * N_ * 3 * H_);
    int r  = warp % (B_ * N_ * 3 * H_);
    int bb = r / (N_ * 3 * H_);
    int nn = (r / (3 * H_)) % N_;
    int ss = (r / H_) % 3;
    int hh = r % H_;

    const float* src = (st ? qkv1 : qkv0)
                     + (long)(bb * N_ + nn) * (3 * C_) + ss * C_ + hh * 64;
    float x0 = src[lane], x1 = src[lane + 32];
    float s = x0 + x1, s2 = x0 * x0 + x1 * x1;
#pragma unroll
    for (int o = 16; o > 0; o >>= 1) {
        s  += __shfl_xor_sync(~0u, s, o);
        s2 += __shfl_xor_sync(~0u, s2, o);
    }
    float mu = s * (1.f / 64.f);
    float var = s2 * (1.f / 64.f) - mu * mu;
    float rs = rsqrtf(var + 1e-5f);

    float* dst;
    if (st == 0) dst = (ss == 0) ? q0 : ((ss == 1) ? k0 : v0);
    else         dst = (ss == 0) ? q1 : ((ss == 1) ? k1 : v1);
    dst += (long)((bb * H_ + hh) * N_ + nn) * 64;
    dst[lane]      = (x0 - mu) * rs * w[lane]      + b[lane];
    dst[lane + 32] = (x1 - mu) * rs * w[lane + 32] + b[lane + 32];
}

// ---------------- 128x128x8 tiled GEMM (8x8 per thread) ----------------
// C[m,n] = alpha * sum_k A[m,k] * (TRANSB ? B[n,k] : B[k,n])
// epilogue: +bias[n]; if GELU -> gelu; then +res1[off] +res2[off]
template <bool TRANSB, bool GELU>
__global__ void __launch_bounds__(256) gemm128(
    const float* __restrict__ A, const float* __restrict__ B,
    const float* __restrict__ bias, const float* __restrict__ res1,
    const float* __restrict__ res2, float* __restrict__ Cout,
    int M, int N, int K, long sA, long sB, long sC, float alpha)
{
    __shared__ float As[8][128];
    __shared__ float Bs[8][128];

    const int z = blockIdx.z;
    const float* Ab = A + z * sA + (long)blockIdx.y * 128 * K;
    const float* Bb = B + z * sB;
    const int nBase = blockIdx.x * 128;
    if (TRANSB) Bb += (long)nBase * K;

    const int tid = threadIdx.x;
    const int ty = tid >> 4, tx = tid & 15;

    float acc[8][8];
#pragma unroll
    for (int i = 0; i < 8; i++)
#pragma unroll
        for (int j = 0; j < 8; j++) acc[i][j] = 0.f;

    const int arow = tid >> 1;
    const int acg  = (tid & 1) * 4;
    const int brow = tid >> 5;         // NN path
    const int bcol = (tid & 31) * 4;   // NN path

    for (int k0 = 0; k0 < K; k0 += 8) {
        float4 av = *(const float4*)(Ab + (long)arow * K + k0 + acg);
        As[acg + 0][arow] = av.x; As[acg + 1][arow] = av.y;
        As[acg + 2][arow] = av.z; As[acg + 3][arow] = av.w;
        if (TRANSB) {
            float4 bv = *(const float4*)(Bb + (long)arow * K + k0 + acg);
            Bs[acg + 0][arow] = bv.x; Bs[acg + 1][arow] = bv.y;
            Bs[acg + 2][arow] = bv.z; Bs[acg + 3][arow] = bv.w;
        } else {
            float4 bv = *(const float4*)(Bb + (long)(k0 + brow) * N + nBase + bcol);
            *(float4*)&Bs[brow][bcol] = bv;
        }
        __syncthreads();
#pragma unroll
        for (int kk = 0; kk < 8; kk++) {
            float4 a0 = *(const float4*)&As[kk][ty * 8];
            float4 a1 = *(const float4*)&As[kk][ty * 8 + 4];
            float4 b0 = *(const float4*)&Bs[kk][tx * 8];
            float4 b1 = *(const float4*)&Bs[kk][tx * 8 + 4];
            float a[8] = {a0.x, a0.y, a0.z, a0.w, a1.x, a1.y, a1.z, a1.w};
            float bbv[8] = {b0.x, b0.y, b0.z, b0.w, b1.x, b1.y, b1.z, b1.w};
#pragma unroll
            for (int i = 0; i < 8; i++)
#pragma unroll
                for (int j = 0; j < 8; j++)
                    acc[i][j] += a[i] * bbv[j];
        }
        __syncthreads();
    }

#pragma unroll
    for (int i = 0; i < 8; i++) {
        int rowg = blockIdx.y * 128 + ty * 8 + i;
#pragma unroll
        for (int j = 0; j < 8; j++) {
            int colg = nBase + tx * 8 + j;
            long off = z * sC + (long)rowg * N + colg;
            float c = acc[i][j] * alpha;
            if (bias) c += bias[colg];
            if (GELU) c = 0.5f * c * (1.0f + erff(c * 0.70710678118654752440f));
            if (res1) c += res1[off];
            if (res2) c += res2[off];
            Cout[off] = c;
        }
    }
}

// ---------------- 64x64x16 NN GEMM (for ctx = P @ V, N=64) ----------------
__global__ void __launch_bounds__(256) gemm64nn(
    const float* __restrict__ A, const float* __restrict__ B,
    float* __restrict__ Cout, int M, int N, int K,
    long sA, long sB, long sC)
{
    __shared__ float As[16][64];
    __shared__ float Bs[16][64];

    const int z = blockIdx.z;
    const float* Ab = A + z * sA + (long)blockIdx.y * 64 * K;
    const float* Bb = B + z * sB;
    const int nBase = blockIdx.x * 64;

    const int tid = threadIdx.x;
    const int ty = tid >> 4, tx = tid & 15;
    const int ar = tid >> 2, ac = (tid & 3) * 4;
    const int br = tid >> 4, bc = (tid & 15) * 4;

    float acc[4][4];
#pragma unroll
    for (int i = 0; i < 4; i++)
#pragma unroll
        for (int j = 0; j < 4; j++) acc[i][j] = 0.f;

    for (int k0 = 0; k0 < K; k0 += 16) {
        float4 av = *(const float4*)(Ab + (long)ar * K + k0 + ac);
        As[ac + 0][ar] = av.x; As[ac + 1][ar] = av.y;
        As[ac + 2][ar] = av.z; As[ac + 3][ar] = av.w;
        float4 bv = *(const float4*)(Bb + (long)(k0 + br) * N + nBase + bc);
        *(float4*)&Bs[br][bc] = bv;
        __syncthreads();
#pragma unroll
        for (int kk = 0; kk < 16; kk++) {
            float4 a = *(const float4*)&As[kk][ty * 4];
            float4 b = *(const float4*)&Bs[kk][tx * 4];
            float aa[4] = {a.x, a.y, a.z, a.w};
            float bb2[4] = {b.x, b.y, b.z, b.w};
#pragma unroll
            for (int i = 0; i < 4; i++)
#pragma unroll
                for (int j = 0; j < 4; j++)
                    acc[i][j] += aa[i] * bb2[j];
        }
        __syncthreads();
    }
#pragma unroll
    for (int i = 0; i < 4; i++) {
        int rowg = blockIdx.y * 64 + ty * 4 + i;
#pragma unroll
        for (int j = 0; j < 4; j++) {
            int colg = nBase + tx * 4 + j;
            Cout[z * sC + (long)rowg * N + colg] = acc[i][j];
        }
    }
}

// ---------------- row softmax over 1024 (one block per row) ----------------
__global__ void __launch_bounds__(256) softmax1024(float* __restrict__ S)
{
    float* r = S + (long)blockIdx.x * 1024;
    const int t = threadIdx.x;
    float v[4];
    float mx = -1e30f;
#pragma unroll
    for (int i = 0; i < 4; i++) { v[i] = r[t + i * 256]; mx = fmaxf(mx, v[i]); }

    __shared__ float redm[8], reds[8];
#pragma unroll
    for (int o = 16; o > 0; o >>= 1) mx = fmaxf(mx, __shfl_xor_sync(~0u, mx, o));
    int wid = t >> 5, lid = t & 31;
    if (lid == 0) redm[wid] = mx;
    __syncthreads();
    if (t < 32) {
        float m = (t < 8) ? redm[t] : -1e30f;
#pragma unroll
        for (int o = 4; o > 0; o >>= 1) m = fmaxf(m, __shfl_xor_sync(~0u, m, o));
        if (t == 0) redm[0] = m;
    }
    __syncthreads();
    mx = redm[0];

    float sum = 0.f;
#pragma unroll
    for (int i = 0; i < 4; i++) { v[i] = expf(v[i] - mx); sum += v[i]; }
#pragma unroll
    for (int o = 16; o > 0; o >>= 1) sum += __shfl_xor_sync(~0u, sum, o);
    if (lid == 0) reds[wid] = sum;
    __syncthreads();
    if (t < 32) {
        float m = (t < 8) ? reds[t] : 0.f;
#pragma unroll
        for (int o = 4; o > 0; o >>= 1) m += __shfl_xor_sync(~0u, m, o);
        if (t == 0) reds[0] = m;
    }
    __syncthreads();
    float inv = 1.f / reds[0];
#pragma unroll
    for (int i = 0; i < 4; i++) r[t + i * 256] = v[i] * inv;
}

// ---------------- (B,H,N,D) -> (B,N,H*D) ----------------
__global__ void __launch_bounds__(256) ctx_to_bnc(
    const float* __restrict__ in, float* __restrict__ out)
{
    long idx = (long)blockIdx.x * 256 + threadIdx.x;
    if (idx >= BNC) return;
    int c  = (int)(idx % C_);
    long bn = idx / C_;
    int n  = (int)(bn % N_);
    int b  = (int)(bn / N_);
    int h  = c >> 6, d = c & 63;
    out[idx] = in[((long)(b * H_ + h) * N_ + n) * 64 + d];
}

// =========================== launch ===========================
extern "C" void kernel_launch(void* const* d_in, const int* in_sizes, int n_in,
                              void* d_out, int out_size)
{
    const float* before = (const float*)d_in[0];
    const float* after  = (const float*)d_in[1];
    const float* n1w  = (const float*)d_in[2];
    const float* n1b  = (const float*)d_in[3];
    const float* qkvw = (const float*)d_in[4];
    const float* hlnw = (const float*)d_in[5];
    const float* hlnb = (const float*)d_in[6];
    const float* projw = (const float*)d_in[7];
    const float* projb = (const float*)d_in[8];
    const float* n2w  = (const float*)d_in[9];
    const float* n2b  = (const float*)d_in[10];
    const float* fc1w = (const float*)d_in[11];
    const float* fc1b = (const float*)d_in[12];
    const float* fc2w = (const float*)d_in[13];
    const float* fc2b = (const float*)d_in[14];

    float* out_before = (float*)d_out;
    float* out_after  = (float*)d_out + BNC;

    float *xn0, *xn1, *qkv0, *qkv1, *q0, *k0, *v0, *q1, *k1, *v1;
    float *S, *ctx, *ctxT, *o0, *o1, *y, *h;
    cudaGetSymbolAddress((void**)&xn0,  g_xn0);
    cudaGetSymbolAddress((void**)&xn1,  g_xn1);
    cudaGetSymbolAddress((void**)&qkv0, g_qkv0);
    cudaGetSymbolAddress((void**)&qkv1, g_qkv1);
    cudaGetSymbolAddress((void**)&q0,   g_q0);
    cudaGetSymbolAddress((void**)&k0,   g_k0);
    cudaGetSymbolAddress((void**)&v0,   g_v0);
    cudaGetSymbolAddress((void**)&q1,   g_q1);
    cudaGetSymbolAddress((void**)&k1,   g_k1);
    cudaGetSymbolAddress((void**)&v1,   g_v1);
    cudaGetSymbolAddress((void**)&S,    g_S);
    cudaGetSymbolAddress((void**)&ctx,  g_ctx);
    cudaGetSymbolAddress((void**)&ctxT, g_ctxT);
    cudaGetSymbolAddress((void**)&o0,   g_o0);
    cudaGetSymbolAddress((void**)&o1,   g_o1);
    cudaGetSymbolAddress((void**)&y,    g_y);
    cudaGetSymbolAddress((void**)&h,    g_h);

    const int M = B_ * N_;  // 8192

    // 1) LN(before) -> xn0, LN(after) -> xn1
    ln768_kernel<<<M, 256>>>(before, n1w, n1b, xn0);
    ln768_kernel<<<M, 256>>>(after,  n1w, n1b, xn1);

    // 2) QKV GEMMs: (8192,768) @ (2304,768)^T
    {
        dim3 g(3 * C_ / 128, M / 128, 1);  // 18 x 64
        gemm128<true, false><<<g, 256>>>(xn0, qkvw, nullptr, nullptr, nullptr,
                                         qkv0, M, 3 * C_, C_, 0, 0, 0, 1.f);
        gemm128<true, false><<<g, 256>>>(xn1, qkvw, nullptr, nullptr, nullptr,
                                         qkv1, M, 3 * C_, C_, 0, 0, 0, 1.f);
    }

    // 3) per-head LN + split to (B,H,N,D)
    {
        int rows = 2 * B_ * N_ * 3 * H_;     // 589824 warps
        headln_kernel<<<rows / 8, 256>>>(qkv0, qkv1, hlnw, hlnb,
                                         q0, k0, v0, q1, k1, v1);
    }

    const long sQK = (long)N_ * D_;     // 65536 per (b,h)
    const long sS  = (long)N_ * N_;     // 1048576 per (b,h)
    const int  BH  = B_ * H_;           // 96

    // ---- direction A: context_a = attn(q0, k1, v1) -> after_o (o1) ----
    {
        dim3 gs(N_ / 128, N_ / 128, BH);   // 8x8x96
        gemm128<true, false><<<gs, 256>>>(q0, k1, nullptr, nullptr, nullptr,
                                          S, N_, N_, D_, sQK, sQK, sS, 0.125f);
        softmax1024<<<BH * N_, 256>>>(S);
        dim3 gc(1, N_ / 64, BH);           // 1x16x96
        gemm64nn<<<gc, 256>>>(S, v1, ctx, N_, D_, N_, sS, sQK, sQK);
        ctx_to_bnc<<<(BNC + 255) / 256, 256>>>(ctx, ctxT);
        dim3 gp(C_ / 128, M / 128, 1);     // 6x64
        // after_o = xn1 + ctxT@projW^T + projb + q0.reshape(B,N,C)
        gemm128<true, false><<<gp, 256>>>(ctxT, projw, projb, xn1, q0,
                                          o1, M, C_, C_, 0, 0, 0, 1.f);
    }

    // ---- direction B: context_b = attn(q1, k0, v0) -> before_o (o0) ----
    {
        dim3 gs(N_ / 128, N_ / 128, BH);
        gemm128<true, false><<<gs, 256>>>(q1, k0, nullptr, nullptr, nullptr,
                                          S, N_, N_, D_, sQK, sQK, sS, 0.125f);
        softmax1024<<<BH * N_, 256>>>(S);
        dim3 gc(1, N_ / 64, BH);
        gemm64nn<<<gc, 256>>>(S, v0, ctx, N_, D_, N_, sS, sQK, sQK);
        ctx_to_bnc<<<(BNC + 255) / 256, 256>>>(ctx, ctxT);
        dim3 gp(C_ / 128, M / 128, 1);
        // before_o = xn0 + ctxT@projW^T + projb + q1.reshape(B,N,C)
        gemm128<true, false><<<gp, 256>>>(ctxT, projw, projb, xn0, q1,
                                          o0, M, C_, C_, 0, 0, 0, 1.f);
    }

    // ---- MLP stream 0 (before): out_before = o0 + fc2(gelu(fc1(LN(o0)))) ----
    {
        ln768_kernel<<<M, 256>>>(o0, n2w, n2b, y);
        dim3 g1(HID_ / 128, M / 128, 1);   // 24x64
        gemm128<true, true><<<g1, 256>>>(y, fc1w, fc1b, nullptr, nullptr,
                                         h, M, HID_, C_, 0, 0, 0, 1.f);
        dim3 g2(C_ / 128, M / 128, 1);
        gemm128<true, false><<<g2, 256>>>(h, fc2w, fc2b, o0, nullptr,
                                          out_before, M, C_, HID_, 0, 0, 0, 1.f);
    }
    // ---- MLP stream 1 (after) ----
    {
        ln768_kernel<<<M, 256>>>(o1, n2w, n2b, y);
        dim3 g1(HID_ / 128, M / 128, 1);
        gemm128<true, true><<<g1, 256>>>(y, fc1w, fc1b, nullptr, nullptr,
                                         h, M, HID_, C_, 0, 0, 0, 1.f);
        dim3 g2(C_ / 128, M / 128, 1);
        gemm128<true, false><<<g2, 256>>>(h, fc2w, fc2b, o1, nullptr,
                                          out_after, M, C_, HID_, 0, 0, 0, 1.f);
    }
}

// round 2
// speedup vs baseline: 5.1569x; 5.1569x over previous
#include <cuda_runtime.h>
#include <cstdint>
#include <math.h>

#define B_   8
#define N_   1024
#define C_   768
#define H_   12
#define D_   64
#define HID_ 3072
#define BNC  6291456      /* B*N*C        */
#define BN3C 18874368     /* B*N*3C       */
#define SSZ  100663296    /* B*H*N*N      */
#define HSZ  25165824     /* B*N*HIDDEN   */

// ---------------- scratch (device globals; no allocation) ----------------
__device__ float g_xn0[BNC], g_xn1[BNC];
__device__ float g_qkv0[BN3C], g_qkv1[BN3C];
__device__ float g_q0[BNC], g_k0[BNC], g_v0[BNC];   // v0/v1 hold V TRANSPOSED: [bh][64][1024]
__device__ float g_q1[BNC], g_k1[BNC], g_v1[BNC];
__device__ float g_S[SSZ];
__device__ float g_ctx[BNC], g_ctxT[BNC];
__device__ float g_o0[BNC], g_o1[BNC];
__device__ float g_y[BNC];
__device__ float g_h[HSZ];

// ---------------- LayerNorm over 768 (one block per row) ----------------
__global__ void __launch_bounds__(256) ln768_kernel(
    const float* __restrict__ x, const float* __restrict__ w,
    const float* __restrict__ b, float* __restrict__ y)
{
    const int row = blockIdx.x;
    const float* xr = x + (long)row * C_;
    float* yr = y + (long)row * C_;
    const int t = threadIdx.x;

    float v[3];
    float s = 0.f, s2 = 0.f;
#pragma unroll
    for (int i = 0; i < 3; i++) {
        float tv = xr[t + i * 256];
        v[i] = tv; s += tv; s2 += tv * tv;
    }
#pragma unroll
    for (int o = 16; o > 0; o >>= 1) {
        s  += __shfl_xor_sync(~0u, s, o);
        s2 += __shfl_xor_sync(~0u, s2, o);
    }
    __shared__ float red[16];
    __shared__ float mu_s, rs_s;
    int wid = t >> 5, lid = t & 31;
    if (lid == 0) { red[wid] = s; red[8 + wid] = s2; }
    __syncthreads();
    if (t == 0) {
        float S = 0.f, S2 = 0.f;
#pragma unroll
        for (int i = 0; i < 8; i++) { S += red[i]; S2 += red[8 + i]; }
        float mu = S / C_;
        float var = S2 / C_ - mu * mu;
        mu_s = mu; rs_s = rsqrtf(var + 1e-5f);
    }
    __syncthreads();
    float mu = mu_s, rs = rs_s;
#pragma unroll
    for (int i = 0; i < 3; i++) {
        int c = t + i * 256;
        yr[c] = (v[i] - mu) * rs * w[c] + b[c];
    }
}

// ---------------- per-head LN (64 elems, one warp per row) ----------------
// input: qkv (B,N,3,H,64); q/k out in (B,H,N,64); v out TRANSPOSED (B,H,64,N)
__global__ void __launch_bounds__(256) headln_kernel(
    const float* __restrict__ qkv0, const float* __restrict__ qkv1,
    const float* __restrict__ w, const float* __restrict__ b,
    float* __restrict__ q0, float* __restrict__ k0, float* __restrict__ v0,
    float* __restrict__ q1, float* __restrict__ k1, float* __restrict__ v1)
{
    const int ROWS = 2 * B_ * N_ * 3 * H_;
    int warp = (blockIdx.x * 256 + threadIdx.x) >> 5;
    int lane = threadIdx.x & 31;
    if (warp >= ROWS) return;

    int st = warp / (B_ * N_ * 3 * H_);
    int r  = warp % (B_ * N_ * 3 * H_);
    int bb = r / (N_ * 3 * H_);
    int nn = (r / (3 * H_)) % N_;
    int ss = (r / H_) % 3;
    int hh = r % H_;

    const float* src = (st ? qkv1 : qkv0)
                     + (long)(bb * N_ + nn) * (3 * C_) + ss * C_ + hh * 64;
    float x0 = src[lane], x1 = src[lane + 32];
    float s = x0 + x1, s2 = x0 * x0 + x1 * x1;
#pragma unroll
    for (int o = 16; o > 0; o >>= 1) {
        s  += __shfl_xor_sync(~0u, s, o);
        s2 += __shfl_xor_sync(~0u, s2, o);
    }
    float mu = s * (1.f / 64.f);
    float var = s2 * (1.f / 64.f) - mu * mu;
    float rs = rsqrtf(var + 1e-5f);
    float y0 = (x0 - mu) * rs * w[lane]      + b[lane];
    float y1 = (x1 - mu) * rs * w[lane + 32] + b[lane + 32];

    long bh = (long)(bb * H_ + hh);
    if (ss == 2) {
        float* dT = (st ? v1 : v0) + bh * 65536;   // [64][1024]
        dT[(long)lane * N_ + nn]        = y0;
        dT[(long)(lane + 32) * N_ + nn] = y1;
    } else {
        float* dst = (ss == 0) ? (st ? q1 : q0) : (st ? k1 : k0);
        dst += bh * 65536 + (long)nn * 64;
        dst[lane]      = y0;
        dst[lane + 32] = y1;
    }
}

// ================= tf32 tensor-core TN GEMM =================
// C[m,n] = alpha * sum_k A[m,k]*B[n,k]  (both row-major, TN)
// BM=128, BN template (128 or 64), BK=32; 256 threads, 8 warps (4x2).
// cp.async 2-stage double buffer; ldmatrix fragment loads; m16n8k8 tf32 mma.

#define LDSM4(R0,R1,R2,R3,ADDR) \
  asm volatile("ldmatrix.sync.aligned.m8n8.x4.shared.b16 {%0,%1,%2,%3}, [%4];" \
    : "=r"(R0),"=r"(R1),"=r"(R2),"=r"(R3) : "r"(ADDR))

#define MMA_TF32(D,A,B0,B1) \
  asm volatile("mma.sync.aligned.m16n8k8.row.col.f32.tf32.tf32.f32 " \
   "{%0,%1,%2,%3}, {%4,%5,%6,%7}, {%8,%9}, {%0,%1,%2,%3};" \
   : "+f"(D[0]),"+f"(D[1]),"+f"(D[2]),"+f"(D[3]) \
   : "r"(A[0]),"r"(A[1]),"r"(A[2]),"r"(A[3]),"r"(B0),"r"(B1))

#define SMST 36   /* smem row stride in floats (144B: 16B-aligned, LDSM conflict-free) */

template <int BN, bool GELU>
__global__ void __launch_bounds__(256) mma_tn(
    const float* __restrict__ A, const float* __restrict__ Bw,
    const float* __restrict__ bias, const float* __restrict__ res1,
    const float* __restrict__ res2, float* __restrict__ Cout,
    int M, int N, int K, long sA, long sB, long sC, float alpha)
{
    constexpr int NT = BN / 16;          // n8-tiles per warp (8 or 4)
    constexpr int ABYTES = 128 * SMST * 4;
    constexpr int BBYTES = BN * SMST * 4;
    constexpr int STAGE  = ABYTES + BBYTES;

    extern __shared__ float sm[];
    const uint32_t smBase = (uint32_t)__cvta_generic_to_shared(sm);

    const int t = threadIdx.x;
    const int z = blockIdx.z;
    const int m0 = blockIdx.y * 128, n0 = blockIdx.x * BN;
    const float* Ab = A  + z * sA + (long)m0 * K;
    const float* Bb = Bw + z * sB + (long)n0 * K;

    const int lane = t & 31;
    const int w = t >> 5;
    const int wm = (w >> 1) * 32;         // warp m offset
    const int wn = (w & 1) * (BN / 2);    // warp n offset

    // cp.async indices: chunk u = t + i*256 -> row u>>3, col4 u&7
    const int rA = t >> 3;
    const int c4 = (t & 7) * 4;

    // ldmatrix per-lane tile mapping
    const int g = lane >> 3, rr = lane & 7;
    const uint32_t aoff = (uint32_t)(((wm + (g & 1) * 8 + rr) * SMST + (g >> 1) * 4) * 4);
    const uint32_t boff = (uint32_t)(((wn + (g >> 1) * 8 + rr) * SMST + (g & 1) * 4) * 4);

    float acc[2][NT][4];
#pragma unroll
    for (int i = 0; i < 2; i++)
#pragma unroll
        for (int j = 0; j < NT; j++)
#pragma unroll
            for (int e = 0; e < 4; e++) acc[i][j][e] = 0.f;

    const int KT = K >> 5;

    auto prefetch = [&](int kt, int s) {
        const long k0 = (long)kt * 32;
        uint32_t da = smBase + s * STAGE;
        uint32_t db = da + ABYTES;
#pragma unroll
        for (int i = 0; i < 4; i++) {
            int row = rA + i * 32;
            uint32_t dst = da + (uint32_t)((row * SMST + c4) * 4);
            const float* src = Ab + (long)row * K + k0 + c4;
            asm volatile("cp.async.cg.shared.global [%0], [%1], 16;" :: "r"(dst), "l"(src));
        }
#pragma unroll
        for (int i = 0; i < BN / 32; i++) {
            int row = rA + i * 32;
            uint32_t dst = db + (uint32_t)((row * SMST + c4) * 4);
            const float* src = Bb + (long)row * K + k0 + c4;
            asm volatile("cp.async.cg.shared.global [%0], [%1], 16;" :: "r"(dst), "l"(src));
        }
        asm volatile("cp.async.commit_group;");
    };

    prefetch(0, 0);

    for (int kt = 0; kt < KT; kt++) {
        const int s = kt & 1;
        if (kt + 1 < KT) {
            prefetch(kt + 1, s ^ 1);
            asm volatile("cp.async.wait_group 1;" ::: "memory");
        } else {
            asm volatile("cp.async.wait_group 0;" ::: "memory");
        }
        __syncthreads();

        const uint32_t aBase = smBase + s * STAGE + aoff;
        const uint32_t bBase = smBase + s * STAGE + ABYTES + boff;

#pragma unroll
        for (int ks = 0; ks < 4; ks++) {
            uint32_t a[2][4];
            LDSM4(a[0][0], a[0][1], a[0][2], a[0][3], aBase + (uint32_t)((ks * 8) * 4));
            LDSM4(a[1][0], a[1][1], a[1][2], a[1][3], aBase + (uint32_t)((16 * SMST + ks * 8) * 4));
            uint32_t b[NT][2];
#pragma unroll
            for (int jp = 0; jp < NT / 2; jp++) {
                LDSM4(b[2 * jp][0], b[2 * jp][1], b[2 * jp + 1][0], b[2 * jp + 1][1],
                      bBase + (uint32_t)((jp * 16 * SMST + ks * 8) * 4));
            }
#pragma unroll
            for (int im = 0; im < 2; im++)
#pragma unroll
                for (int jn = 0; jn < NT; jn++)
                    MMA_TF32(acc[im][jn], a[im], b[jn][0], b[jn][1]);
        }
        __syncthreads();
    }

    // epilogue
#pragma unroll
    for (int im = 0; im < 2; im++) {
        int r_lo = m0 + wm + im * 16 + (lane >> 2);
#pragma unroll
        for (int jn = 0; jn < NT; jn++) {
            int col = n0 + wn + jn * 8 + (lane & 3) * 2;
#pragma unroll
            for (int hh = 0; hh < 2; hh++) {
                int rowg = r_lo + hh * 8;
                float c0 = acc[im][jn][hh * 2 + 0] * alpha;
                float c1 = acc[im][jn][hh * 2 + 1] * alpha;
                if (bias) { c0 += bias[col]; c1 += bias[col + 1]; }
                if (GELU) {
                    c0 = 0.5f * c0 * (1.0f + erff(c0 * 0.70710678118654752440f));
                    c1 = 0.5f * c1 * (1.0f + erff(c1 * 0.70710678118654752440f));
                }
                long off = z * sC + (long)rowg * N + col;
                if (res1) { c0 += res1[off]; c1 += res1[off + 1]; }
                if (res2) { c0 += res2[off]; c1 += res2[off + 1]; }
                float2 v2; v2.x = c0; v2.y = c1;
                *(float2*)(Cout + off) = v2;
            }
        }
    }
}

// ---------------- row softmax over 1024 (one block per row) ----------------
__global__ void __launch_bounds__(256) softmax1024(float* __restrict__ S)
{
    float* r = S + (long)blockIdx.x * 1024;
    const int t = threadIdx.x;
    float v[4];
    float mx = -1e30f;
#pragma unroll
    for (int i = 0; i < 4; i++) { v[i] = r[t + i * 256]; mx = fmaxf(mx, v[i]); }

    __shared__ float redm[8], reds[8];
#pragma unroll
    for (int o = 16; o > 0; o >>= 1) mx = fmaxf(mx, __shfl_xor_sync(~0u, mx, o));
    int wid = t >> 5, lid = t & 31;
    if (lid == 0) redm[wid] = mx;
    __syncthreads();
    if (t < 32) {
        float m = (t < 8) ? redm[t] : -1e30f;
#pragma unroll
        for (int o = 4; o > 0; o >>= 1) m = fmaxf(m, __shfl_xor_sync(~0u, m, o));
        if (t == 0) redm[0] = m;
    }
    __syncthreads();
    mx = redm[0];

    float sum = 0.f;
#pragma unroll
    for (int i = 0; i < 4; i++) { v[i] = expf(v[i] - mx); sum += v[i]; }
#pragma unroll
    for (int o = 16; o > 0; o >>= 1) sum += __shfl_xor_sync(~0u, sum, o);
    if (lid == 0) reds[wid] = sum;
    __syncthreads();
    if (t < 32) {
        float m = (t < 8) ? reds[t] : 0.f;
#pragma unroll
        for (int o = 4; o > 0; o >>= 1) m += __shfl_xor_sync(~0u, m, o);
        if (t == 0) reds[0] = m;
    }
    __syncthreads();
    float inv = 1.f / reds[0];
#pragma unroll
    for (int i = 0; i < 4; i++) r[t + i * 256] = v[i] * inv;
}

// ---------------- (B,H,N,D) -> (B,N,H*D) ----------------
__global__ void __launch_bounds__(256) ctx_to_bnc(
    const float* __restrict__ in, float* __restrict__ out)
{
    long idx = (long)blockIdx.x * 256 + threadIdx.x;
    if (idx >= BNC) return;
    int c  = (int)(idx % C_);
    long bn = idx / C_;
    int n  = (int)(bn % N_);
    int b  = (int)(bn / N_);
    int h  = c >> 6, d = c & 63;
    out[idx] = in[((long)(b * H_ + h) * N_ + n) * 64 + d];
}

// =========================== launch ===========================
extern "C" void kernel_launch(void* const* d_in, const int* in_sizes, int n_in,
                              void* d_out, int out_size)
{
    const float* before = (const float*)d_in[0];
    const float* after  = (const float*)d_in[1];
    const float* n1w  = (const float*)d_in[2];
    const float* n1b  = (const float*)d_in[3];
    const float* qkvw = (const float*)d_in[4];
    const float* hlnw = (const float*)d_in[5];
    const float* hlnb = (const float*)d_in[6];
    const float* projw = (const float*)d_in[7];
    const float* projb = (const float*)d_in[8];
    const float* n2w  = (const float*)d_in[9];
    const float* n2b  = (const float*)d_in[10];
    const float* fc1w = (const float*)d_in[11];
    const float* fc1b = (const float*)d_in[12];
    const float* fc2w = (const float*)d_in[13];
    const float* fc2b = (const float*)d_in[14];

    float* out_before = (float*)d_out;
    float* out_after  = (float*)d_out + BNC;

    float *xn0, *xn1, *qkv0, *qkv1, *q0, *k0, *v0, *q1, *k1, *v1;
    float *S, *ctx, *ctxT, *o0, *o1, *y, *h;
    cudaGetSymbolAddress((void**)&xn0,  g_xn0);
    cudaGetSymbolAddress((void**)&xn1,  g_xn1);
    cudaGetSymbolAddress((void**)&qkv0, g_qkv0);
    cudaGetSymbolAddress((void**)&qkv1, g_qkv1);
    cudaGetSymbolAddress((void**)&q0,   g_q0);
    cudaGetSymbolAddress((void**)&k0,   g_k0);
    cudaGetSymbolAddress((void**)&v0,   g_v0);
    cudaGetSymbolAddress((void**)&q1,   g_q1);
    cudaGetSymbolAddress((void**)&k1,   g_k1);
    cudaGetSymbolAddress((void**)&v1,   g_v1);
    cudaGetSymbolAddress((void**)&S,    g_S);
    cudaGetSymbolAddress((void**)&ctx,  g_ctx);
    cudaGetSymbolAddress((void**)&ctxT, g_ctxT);
    cudaGetSymbolAddress((void**)&o0,   g_o0);
    cudaGetSymbolAddress((void**)&o1,   g_o1);
    cudaGetSymbolAddress((void**)&y,    g_y);
    cudaGetSymbolAddress((void**)&h,    g_h);

    // opt-in dynamic smem (idempotent, host-side, capture-safe)
    cudaFuncSetAttribute(mma_tn<128, false>, cudaFuncAttributeMaxDynamicSharedMemorySize, 73728);
    cudaFuncSetAttribute(mma_tn<128, true>,  cudaFuncAttributeMaxDynamicSharedMemorySize, 73728);
    cudaFuncSetAttribute(mma_tn<64,  false>, cudaFuncAttributeMaxDynamicSharedMemorySize, 55296);

    const int M = B_ * N_;  // 8192
    const long sQK = (long)N_ * D_;     // 65536 per (b,h)
    const long sS  = (long)N_ * N_;     // 1048576 per (b,h)
    const int  BH  = B_ * H_;           // 96
    const int SM128 = 73728, SM64 = 55296;

    // 1) LN
    ln768_kernel<<<M, 256>>>(before, n1w, n1b, xn0);
    ln768_kernel<<<M, 256>>>(after,  n1w, n1b, xn1);

    // 2) QKV GEMMs (8192,768)@(2304,768)^T
    {
        dim3 g(3 * C_ / 128, M / 128, 1);
        mma_tn<128, false><<<g, 256, SM128>>>(xn0, qkvw, nullptr, nullptr, nullptr,
                                              qkv0, M, 3 * C_, C_, 0, 0, 0, 1.f);
        mma_tn<128, false><<<g, 256, SM128>>>(xn1, qkvw, nullptr, nullptr, nullptr,
                                              qkv1, M, 3 * C_, C_, 0, 0, 0, 1.f);
    }

    // 3) per-head LN + split (v transposed)
    {
        int rows = 2 * B_ * N_ * 3 * H_;
        headln_kernel<<<rows / 8, 256>>>(qkv0, qkv1, hlnw, hlnb,
                                         q0, k0, v0, q1, k1, v1);
    }

    // ---- direction A: context_a = attn(q0, k1, v1) -> after_o (o1) ----
    {
        dim3 gs(N_ / 128, N_ / 128, BH);
        mma_tn<128, false><<<gs, 256, SM128>>>(q0, k1, nullptr, nullptr, nullptr,
                                               S, N_, N_, D_, sQK, sQK, sS, 0.125f);
        softmax1024<<<BH * N_, 256>>>(S);
        dim3 gc(1, N_ / 128, BH);
        mma_tn<64, false><<<gc, 256, SM64>>>(S, v1, nullptr, nullptr, nullptr,
                                             ctx, N_, D_, N_, sS, sQK, sQK, 1.f);
        ctx_to_bnc<<<(BNC + 255) / 256, 256>>>(ctx, ctxT);
        dim3 gp(C_ / 128, M / 128, 1);
        mma_tn<128, false><<<gp, 256, SM128>>>(ctxT, projw, projb, xn1, q0,
                                               o1, M, C_, C_, 0, 0, 0, 1.f);
    }

    // ---- direction B: context_b = attn(q1, k0, v0) -> before_o (o0) ----
    {
        dim3 gs(N_ / 128, N_ / 128, BH);
        mma_tn<128, false><<<gs, 256, SM128>>>(q1, k0, nullptr, nullptr, nullptr,
                                               S, N_, N_, D_, sQK, sQK, sS, 0.125f);
        softmax1024<<<BH * N_, 256>>>(S);
        dim3 gc(1, N_ / 128, BH);
        mma_tn<64, false><<<gc, 256, SM64>>>(S, v0, nullptr, nullptr, nullptr,
                                             ctx, N_, D_, N_, sS, sQK, sQK, 1.f);
        ctx_to_bnc<<<(BNC + 255) / 256, 256>>>(ctx, ctxT);
        dim3 gp(C_ / 128, M / 128, 1);
        mma_tn<128, false><<<gp, 256, SM128>>>(ctxT, projw, projb, xn0, q1,
                                               o0, M, C_, C_, 0, 0, 0, 1.f);
    }

    // ---- MLP stream 0 (before) ----
    {
        ln768_kernel<<<M, 256>>>(o0, n2w, n2b, y);
        dim3 g1(HID_ / 128, M / 128, 1);
        mma_tn<128, true><<<g1, 256, SM128>>>(y, fc1w, fc1b, nullptr, nullptr,
                                              h, M, HID_, C_, 0, 0, 0, 1.f);
        dim3 g2(C_ / 128, M / 128, 1);
        mma_tn<128, false><<<g2, 256, SM128>>>(h, fc2w, fc2b, o0, nullptr,
                                               out_before, M, C_, HID_, 0, 0, 0, 1.f);
    }
    // ---- MLP stream 1 (after) ----
    {
        ln768_kernel<<<M, 256>>>(o1, n2w, n2b, y);
        dim3 g1(HID_ / 128, M / 128, 1);
        mma_tn<128, true><<<g1, 256, SM128>>>(y, fc1w, fc1b, nullptr, nullptr,
                                              h, M, HID_, C_, 0, 0, 0, 1.f);
        dim3 g2(C_ / 128, M / 128, 1);
        mma_tn<128, false><<<g2, 256, SM128>>>(h, fc2w, fc2b, o1, nullptr,
                                               out_after, M, C_, HID_, 0, 0, 0, 1.f);
    }
}